// round 2
// baseline (speedup 1.0000x reference)
#include <cuda_runtime.h>
#include <cstdint>

#define NG    1000
#define NODES 100
#define EDGES 1600
#define NTOT  100000
#define ETOT  1600000
#define HID   128
#define KTOP  40

// ---------------- scratch (device globals; no runtime allocation) ----------
__device__ float g_X0[(size_t)NTOT * HID];
__device__ float g_X1[(size_t)NTOT * HID];
__device__ float g_X2[(size_t)NTOT * HID];
__device__ int   g_off [NG * 101];
__device__ int   g_srcl[ETOT];
__device__ float g_normv[ETOT];

// ---------------- helpers ---------------------------------------------------
__device__ __forceinline__ float acc_tanh(float x) {
    float xc = fminf(fmaxf(x, -10.f), 10.f);
    float e  = __expf(2.f * xc);
    return (e - 1.f) / (e + 1.f);
}
__device__ __forceinline__ uint32_t f2tf32(float x) {
    uint32_t r;
    asm("cvt.rna.tf32.f32 %0, %1;" : "=r"(r) : "f"(x));
    return r;
}
__device__ __forceinline__ void mma_tf32(float c[4], const uint32_t a[4],
                                         const uint32_t b0, const uint32_t b1) {
    asm volatile(
        "mma.sync.aligned.m16n8k8.row.col.f32.tf32.tf32.f32 "
        "{%0,%1,%2,%3}, {%4,%5,%6,%7}, {%8,%9}, {%0,%1,%2,%3};\n"
        : "+f"(c[0]), "+f"(c[1]), "+f"(c[2]), "+f"(c[3])
        : "r"(a[0]), "r"(a[1]), "r"(a[2]), "r"(a[3]), "r"(b0), "r"(b1));
}

// ---------------- kernel 1: deterministic per-graph CSR --------------------
__global__ void __launch_bounds__(256) build_csr(const int* __restrict__ ei)
{
    __shared__ int   sdst[EDGES];
    __shared__ int   ssrc[EDGES];
    __shared__ int   deg[NODES];
    __shared__ float dinv[NODES];
    __shared__ int   offs[NODES + 1];

    const int g = blockIdx.x, tid = threadIdx.x;
    const int base = g * NODES;
    const int* srce = ei + (size_t)g * EDGES;
    const int* dste = ei + (size_t)ETOT + (size_t)g * EDGES;

    if (tid < NODES) deg[tid] = 0;
    __syncthreads();

    for (int e = tid; e < EDGES; e += 256) {
        int s = srce[e] - base;
        int d = dste[e] - base;
        ssrc[e] = s;
        sdst[e] = d;
        atomicAdd(&deg[d], 1);
    }
    __syncthreads();

    if (tid < NODES)
        dinv[tid] = deg[tid] > 0 ? rsqrtf((float)deg[tid]) : 0.f;
    if (tid == 0) {
        int acc = 0;
        for (int i = 0; i < NODES; i++) { offs[i] = acc; acc += deg[i]; }
        offs[NODES] = acc;
    }
    __syncthreads();

    if (tid <= NODES) g_off[g * 101 + tid] = offs[tid];

    const int lane = tid & 31, warp = tid >> 5;
    const size_t gb = (size_t)g * EDGES;
    for (int d = warp; d < NODES; d += 8) {
        int pos = offs[d];
        float dd = dinv[d];
        for (int eb = 0; eb < EDGES; eb += 32) {
            int e = eb + lane;
            bool m = (sdst[e] == d);
            unsigned mask = __ballot_sync(0xffffffffu, m);
            if (m) {
                int idx = pos + __popc(mask & ((1u << lane) - 1));
                int s = ssrc[e];
                g_srcl [gb + idx] = s;
                g_normv[gb + idx] = dinv[s] * dd;
            }
            pos += __popc(mask);
        }
    }
}

// ---------------- fused layer: T = X@W (tensor core, 3xTF32) -> agg -> tanh -
// one CTA per graph. SMEM: Xh/Xl [128][132] resident, W k16 panels staged.
#define XS 132
#define FUSED_SMEM ((128 * XS * 2 + 16 * XS * 2) * 4)

template <int LAYER0>
__global__ void __launch_bounds__(256, 1) fused_layer(
    const float* __restrict__ A_in, const int* __restrict__ z,
    const float* __restrict__ ztab, const float* __restrict__ xin,
    const float* __restrict__ W,    const float* __restrict__ bias,
    float* __restrict__ Xout)
{
    extern __shared__ float sm[];
    float* Xh = sm;                    // 128*132
    float* Xl = Xh + 128 * XS;         // 128*132
    float* Wh = Xl + 128 * XS;         // 16*132
    float* Wl = Wh + 16 * XS;          // 16*132
    float* Ts = Xh;                    // alias after GEMM

    const int g = blockIdx.x, tid = threadIdx.x;
    const int lane = tid & 31, wid = tid >> 5;
    const int wm = wid & 1, wn = wid >> 1;      // 2 x 4 warp grid

    float acc[4][4][4];
#pragma unroll
    for (int mi = 0; mi < 4; mi++)
#pragma unroll
        for (int nj = 0; nj < 4; nj++)
#pragma unroll
            for (int q = 0; q < 4; q++) acc[mi][nj][q] = 0.f;

    const int KH = LAYER0 ? 2 : 1;
    for (int kh = 0; kh < KH; kh++) {
        // ---- load A panel [100 x 128] as tf32 hi + fp32 lo -----------------
        __syncthreads();
        for (int t = tid; t < NODES * 32; t += 256) {
            int r = t >> 5, c4 = (t & 31) << 2;
            const float* src;
            if (LAYER0)
                src = (kh == 0)
                    ? (ztab + (size_t)z[g * NODES + r] * HID + c4)
                    : (xin + ((size_t)g * NODES + r) * HID + c4);
            else
                src = A_in + ((size_t)g * NODES + r) * HID + c4;
            float4 v = *(const float4*)src;
            float4 h, l;
            h.x = __uint_as_float(f2tf32(v.x)); l.x = v.x - h.x;
            h.y = __uint_as_float(f2tf32(v.y)); l.y = v.y - h.y;
            h.z = __uint_as_float(f2tf32(v.z)); l.z = v.z - h.z;
            h.w = __uint_as_float(f2tf32(v.w)); l.w = v.w - h.w;
            *(float4*)&Xh[r * XS + c4] = h;
            *(float4*)&Xl[r * XS + c4] = l;
        }
        __syncthreads();

        for (int kp = 0; kp < 8; kp++) {
            // ---- stage W panel rows [kh*128 + kp*16, +16) ------------------
            __syncthreads();
            for (int t = tid; t < 512; t += 256) {
                int r = t >> 5, c4 = (t & 31) << 2;
                float4 v = *(const float4*)(W +
                    ((size_t)(kh * 128 + kp * 16 + r)) * HID + c4);
                float4 h, l;
                h.x = __uint_as_float(f2tf32(v.x)); l.x = v.x - h.x;
                h.y = __uint_as_float(f2tf32(v.y)); l.y = v.y - h.y;
                h.z = __uint_as_float(f2tf32(v.z)); l.z = v.z - h.z;
                h.w = __uint_as_float(f2tf32(v.w)); l.w = v.w - h.w;
                *(float4*)&Wh[r * XS + c4] = h;
                *(float4*)&Wl[r * XS + c4] = l;
            }
            __syncthreads();

#pragma unroll
            for (int k8 = 0; k8 < 2; k8++) {
                const int kc = kp * 16 + k8 * 8;  // A col
                const int kw = k8 * 8;            // W panel row
                const int brow = kw + (lane & 3);
                const int bcol = lane >> 2;
                uint32_t bh[4][2], bl[4][2];
#pragma unroll
                for (int nj = 0; nj < 4; nj++) {
                    int n0 = (wn * 4 + nj) * 8 + bcol;
                    bh[nj][0] = __float_as_uint(Wh[brow * XS + n0]);
                    bh[nj][1] = __float_as_uint(Wh[(brow + 4) * XS + n0]);
                    bl[nj][0] = __float_as_uint(Wl[brow * XS + n0]);
                    bl[nj][1] = __float_as_uint(Wl[(brow + 4) * XS + n0]);
                }
#pragma unroll
                for (int mi = 0; mi < 4; mi++) {
                    int ar = (wm * 4 + mi) * 16 + (lane >> 2);
                    int ac = kc + (lane & 3);
                    uint32_t ah[4], al[4];
                    ah[0] = __float_as_uint(Xh[ar * XS + ac]);
                    ah[1] = __float_as_uint(Xh[(ar + 8) * XS + ac]);
                    ah[2] = __float_as_uint(Xh[ar * XS + ac + 4]);
                    ah[3] = __float_as_uint(Xh[(ar + 8) * XS + ac + 4]);
                    al[0] = __float_as_uint(Xl[ar * XS + ac]);
                    al[1] = __float_as_uint(Xl[(ar + 8) * XS + ac]);
                    al[2] = __float_as_uint(Xl[ar * XS + ac + 4]);
                    al[3] = __float_as_uint(Xl[(ar + 8) * XS + ac + 4]);
#pragma unroll
                    for (int nj = 0; nj < 4; nj++) {
                        mma_tf32(acc[mi][nj], ah, bh[nj][0], bh[nj][1]);
                        mma_tf32(acc[mi][nj], ah, bl[nj][0], bl[nj][1]);
                        mma_tf32(acc[mi][nj], al, bh[nj][0], bh[nj][1]);
                    }
                }
            }
        }
    }
    __syncthreads();

    // ---- write T into SMEM (alias Xh) --------------------------------------
#pragma unroll
    for (int mi = 0; mi < 4; mi++) {
#pragma unroll
        for (int nj = 0; nj < 4; nj++) {
            int r  = (wm * 4 + mi) * 16 + (lane >> 2);
            int cn = (wn * 4 + nj) * 8 + 2 * (lane & 3);
            Ts[r * XS + cn]           = acc[mi][nj][0];
            Ts[r * XS + cn + 1]       = acc[mi][nj][1];
            Ts[(r + 8) * XS + cn]     = acc[mi][nj][2];
            Ts[(r + 8) * XS + cn + 1] = acc[mi][nj][3];
        }
    }
    __syncthreads();

    // ---- aggregation + tanh -------------------------------------------------
    const float4 bv = *(const float4*)(bias + lane * 4);
    const int*   srcp = g_srcl + (size_t)g * EDGES;
    const float* nvp  = g_normv + (size_t)g * EDGES;
    const int*   offp = g_off + g * 101;

    for (int d = wid; d < NODES; d += 8) {
        int e0 = offp[d], e1 = offp[d + 1];
        float4 a4 = make_float4(0.f, 0.f, 0.f, 0.f);
        for (int e = e0; e < e1; e++) {
            int s = srcp[e];
            float w = nvp[e];
            float4 tv = *(const float4*)&Ts[s * XS + lane * 4];
            a4.x += w * tv.x; a4.y += w * tv.y;
            a4.z += w * tv.z; a4.w += w * tv.w;
        }
        float4 o;
        o.x = acc_tanh(a4.x + bv.x);
        o.y = acc_tanh(a4.y + bv.y);
        o.z = acc_tanh(a4.z + bv.z);
        o.w = acc_tanh(a4.w + bv.w);
        *(float4*)(Xout + ((size_t)g * NODES + d) * HID + lane * 4) = o;
    }
}

// ---------------- final: layer3 + sort-pool + conv + MLP --------------------
#define FINAL_SMEM_FLOATS 39028
__global__ void __launch_bounds__(256) final_k(
    const float* __restrict__ W3,  const float* __restrict__ b3,
    const float* __restrict__ cw1, const float* __restrict__ cb1,
    const float* __restrict__ cw2, const float* __restrict__ cb2,
    const float* __restrict__ mW1, const float* __restrict__ mb1,
    const float* __restrict__ mW2, const float* __restrict__ mb2,
    float* __restrict__ out)
{
    extern __shared__ float sm[];
    float* X2s  = sm;                  // 100*129
    float* cw1s = X2s + 100 * 129;     // 16*388 = 6208
    float* feat = cw1s + 6208;         // 40*388 = 15520
    float* cw2s = feat + 15520;        // 2560
    float* t3   = cw2s + 2560;         // 100
    float* x3   = t3 + 100;            // 100
    float* y1   = x3 + 100;            // 640 (reused as mlp1 partials)
    float* mmp  = y1 + 640;            // 320
    float* flat = mmp + 320;           // 512
    float* rr   = flat + 512;          // 128
    int*   topi = (int*)(rr + 128);    // 40

    const int g = blockIdx.x, tid = threadIdx.x;
    const float* X2g = g_X2 + (size_t)g * NODES * HID;

    for (int t = tid; t < NODES * HID; t += 256) {
        int i = t >> 7, d = t & 127;
        X2s[i * 129 + d] = X2g[t];
    }
    for (int t = tid; t < 16 * 385; t += 256) {
        int c = t / 385, d = t - c * 385;
        cw1s[c * 388 + d] = cw1[t];
    }
    if (tid < 16) {
        cw1s[tid * 388 + 385] = 0.f;
        cw1s[tid * 388 + 386] = 0.f;
        cw1s[tid * 388 + 387] = 0.f;
    }
    for (int t = tid; t < 2560; t += 256) cw2s[t] = cw2[t];
    __syncthreads();

    // ---- layer 3: t3 = X2 @ W3 ---------------------------------------------
    if (tid < NODES) {
        float a = 0.f;
#pragma unroll 8
        for (int k = 0; k < HID; k++) a += X2s[tid * 129 + k] * W3[k];
        t3[tid] = a;
    }
    __syncthreads();

    // ---- x3 = tanh(A @ t3 + b3) --------------------------------------------
    if (tid < NODES) {
        const int*   offp = g_off + g * 101;
        const int*   srcp = g_srcl + (size_t)g * EDGES;
        const float* nvp  = g_normv + (size_t)g * EDGES;
        float a = 0.f;
        int e1 = offp[tid + 1];
        for (int e = offp[tid]; e < e1; e++) a += nvp[e] * t3[srcp[e]];
        x3[tid] = acc_tanh(a + b3[0]);
    }
    __syncthreads();

    // ---- stable descending rank --------------------------------------------
    if (tid < NODES) {
        float v = x3[tid];
        int r = 0;
        for (int j = 0; j < NODES; j++) {
            float u = x3[j];
            r += (u > v) || (u == v && j < tid);
        }
        if (r < KTOP) topi[r] = tid;
    }
    __syncthreads();

    // ---- gather feat rows of top-K nodes -----------------------------------
    for (int t = tid; t < KTOP * HID; t += 256) {
        int k = t >> 7, d = t & 127;
        int node = topi[k];
        size_t gbase = ((size_t)g * NODES + node) * HID;
        feat[k * 388 + d]       = g_X0[gbase + d];
        feat[k * 388 + 128 + d] = g_X1[gbase + d];
        feat[k * 388 + 256 + d] = X2s[node * 129 + d];
    }
    if (tid < KTOP) {
        feat[tid * 388 + 384] = x3[topi[tid]];
        feat[tid * 388 + 385] = 0.f;
        feat[tid * 388 + 386] = 0.f;
        feat[tid * 388 + 387] = 0.f;
    }
    __syncthreads();

    // ---- conv1 + relu (float4 dot over padded 388) --------------------------
    for (int o = tid; o < 640; o += 256) {
        int c = o & 15, kp = o >> 4;
        float a = cb1[c];
        const float4* wr = (const float4*)(cw1s + c * 388);
        const float4* fr = (const float4*)(feat + kp * 388);
#pragma unroll 4
        for (int d = 0; d < 97; d++) {
            float4 w4 = wr[d], f4 = fr[d];
            a += w4.x * f4.x + w4.y * f4.y + w4.z * f4.z + w4.w * f4.w;
        }
        y1[c * 40 + kp] = fmaxf(a, 0.f);
    }
    __syncthreads();

    // ---- maxpool(2,2) -------------------------------------------------------
    for (int t = tid; t < 320; t += 256) {
        int c = t / 20, p = t % 20;
        mmp[t] = fmaxf(y1[c * 40 + 2 * p], y1[c * 40 + 2 * p + 1]);
    }
    __syncthreads();

    // ---- conv2 (16->32, k=5) + relu -----------------------------------------
    for (int t = tid; t < 512; t += 256) {
        int o2 = t >> 4, p = t & 15;
        float a = cb2[o2];
#pragma unroll
        for (int c = 0; c < 16; c++)
#pragma unroll
            for (int u = 0; u < 5; u++)
                a += cw2s[(o2 * 16 + c) * 5 + u] * mmp[c * 20 + p + u];
        flat[t] = fmaxf(a, 0.f);
    }
    __syncthreads();

    // ---- mlp1 (split-K over 2 thread groups) --------------------------------
    {
        int col = tid & 127, half = tid >> 7;
        float a = 0.f;
        const float* fp = flat + half * 256;
        const float* wp = mW1 + (size_t)(half * 256) * 128 + col;
#pragma unroll 8
        for (int i = 0; i < 256; i++) a += fp[i] * wp[(size_t)i * 128];
        y1[tid] = a;
    }
    __syncthreads();
    if (tid < 128) rr[tid] = fmaxf(y1[tid] + y1[tid + 128] + mb1[tid], 0.f);
    __syncthreads();

    // ---- mlp2 + write -------------------------------------------------------
    if (tid < 32) {
        float s = 0.f;
#pragma unroll
        for (int q = 0; q < 4; q++) s += rr[tid + 32 * q] * mW2[tid + 32 * q];
        for (int off2 = 16; off2 > 0; off2 >>= 1)
            s += __shfl_down_sync(0xffffffffu, s, off2);
        if (tid == 0) out[g] = s + mb2[0];
    }
}

// ---------------- host ------------------------------------------------------
extern "C" void kernel_launch(void* const* d_in, const int* in_sizes, int n_in,
                              void* d_out, int out_size)
{
    const float* x    = (const float*)d_in[0];
    const int*   z    = (const int*)  d_in[1];
    const int*   ei   = (const int*)  d_in[2];
    const float* ztab = (const float*)d_in[4];
    const float* W0   = (const float*)d_in[5];
    const float* b0   = (const float*)d_in[6];
    const float* W1   = (const float*)d_in[7];
    const float* b1   = (const float*)d_in[8];
    const float* W2   = (const float*)d_in[9];
    const float* b2   = (const float*)d_in[10];
    const float* W3   = (const float*)d_in[11];
    const float* b3   = (const float*)d_in[12];
    const float* cw1  = (const float*)d_in[13];
    const float* cb1  = (const float*)d_in[14];
    const float* cw2  = (const float*)d_in[15];
    const float* cb2  = (const float*)d_in[16];
    const float* mW1  = (const float*)d_in[17];
    const float* mb1  = (const float*)d_in[18];
    const float* mW2  = (const float*)d_in[19];
    const float* mb2  = (const float*)d_in[20];
    float* out = (float*)d_out;

    float *X0, *X1, *X2;
    cudaGetSymbolAddress((void**)&X0, g_X0);
    cudaGetSymbolAddress((void**)&X1, g_X1);
    cudaGetSymbolAddress((void**)&X2, g_X2);

    cudaFuncSetAttribute(fused_layer<1>, cudaFuncAttributeMaxDynamicSharedMemorySize, FUSED_SMEM);
    cudaFuncSetAttribute(fused_layer<0>, cudaFuncAttributeMaxDynamicSharedMemorySize, FUSED_SMEM);
    cudaFuncSetAttribute(final_k, cudaFuncAttributeMaxDynamicSharedMemorySize, FINAL_SMEM_FLOATS * 4);

    build_csr<<<NG, 256>>>(ei);

    fused_layer<1><<<NG, 256, FUSED_SMEM>>>(nullptr, z, ztab, x, W0, b0, X0);
    fused_layer<0><<<NG, 256, FUSED_SMEM>>>(X0, nullptr, nullptr, nullptr, W1, b1, X1);
    fused_layer<0><<<NG, 256, FUSED_SMEM>>>(X1, nullptr, nullptr, nullptr, W2, b2, X2);

    final_k<<<NG, 256, FINAL_SMEM_FLOATS * 4>>>(W3, b3, cw1, cb1, cw2, cb2,
                                                mW1, mb1, mW2, mb2, out);
}

// round 3
// speedup vs baseline: 1.3905x; 1.3905x over previous
#include <cuda_runtime.h>
#include <cstdint>

#define NG    1000
#define NODES 100
#define EDGES 1600
#define NTOT  100000
#define ETOT  1600000
#define HID   128
#define KTOP  40

// ---------------- scratch (device globals; no runtime allocation) ----------
__device__ float g_T [(size_t)NTOT * HID];
__device__ float g_X0[(size_t)NTOT * HID];
__device__ float g_X1[(size_t)NTOT * HID];
__device__ float g_X2[(size_t)NTOT * HID];
__device__ int   g_off [NG * 101];
__device__ int2  g_edge[ETOT];   // (src, bitcast norm)

// ---------------- helpers ---------------------------------------------------
__device__ __forceinline__ float acc_tanh(float x) {
    float xc = fminf(fmaxf(x, -10.f), 10.f);
    float e  = __expf(2.f * xc);
    return (e - 1.f) / (e + 1.f);
}
__device__ __forceinline__ float f2tf32f(float x) {
    uint32_t r;
    asm("cvt.rna.tf32.f32 %0, %1;" : "=r"(r) : "f"(x));
    return __uint_as_float(r);
}
__device__ __forceinline__ void mma_tf32(float c[4], const uint32_t a[4],
                                         const uint32_t b0, const uint32_t b1) {
    asm volatile(
        "mma.sync.aligned.m16n8k8.row.col.f32.tf32.tf32.f32 "
        "{%0,%1,%2,%3}, {%4,%5,%6,%7}, {%8,%9}, {%0,%1,%2,%3};\n"
        : "+f"(c[0]), "+f"(c[1]), "+f"(c[2]), "+f"(c[3])
        : "r"(a[0]), "r"(a[1]), "r"(a[2]), "r"(a[3]), "r"(b0), "r"(b1));
}

// ---------------- kernel 1: deterministic per-graph CSR --------------------
__global__ void __launch_bounds__(256) build_csr(const int* __restrict__ ei)
{
    __shared__ int   sdst[EDGES];
    __shared__ int   ssrc[EDGES];
    __shared__ int   deg[NODES];
    __shared__ float dinv[NODES];
    __shared__ int   offs[NODES + 1];

    const int g = blockIdx.x, tid = threadIdx.x;
    const int base = g * NODES;
    const int* srce = ei + (size_t)g * EDGES;
    const int* dste = ei + (size_t)ETOT + (size_t)g * EDGES;

    if (tid < NODES) deg[tid] = 0;
    __syncthreads();

    for (int e = tid; e < EDGES; e += 256) {
        int s = srce[e] - base;
        int d = dste[e] - base;
        ssrc[e] = s;
        sdst[e] = d;
        atomicAdd(&deg[d], 1);
    }
    __syncthreads();

    if (tid < NODES)
        dinv[tid] = deg[tid] > 0 ? rsqrtf((float)deg[tid]) : 0.f;
    if (tid == 0) {
        int acc = 0;
        for (int i = 0; i < NODES; i++) { offs[i] = acc; acc += deg[i]; }
        offs[NODES] = acc;
    }
    __syncthreads();

    if (tid <= NODES) g_off[g * 101 + tid] = offs[tid];

    const int lane = tid & 31, warp = tid >> 5;
    const size_t gb = (size_t)g * EDGES;
    for (int d = warp; d < NODES; d += 8) {
        int pos = offs[d];
        float dd = dinv[d];
        for (int eb = 0; eb < EDGES; eb += 32) {
            int e = eb + lane;
            bool m = (sdst[e] == d);
            unsigned mask = __ballot_sync(0xffffffffu, m);
            if (m) {
                int idx = pos + __popc(mask & ((1u << lane) - 1));
                int s = ssrc[e];
                g_edge[gb + idx] = make_int2(s, __float_as_int(dinv[s] * dd));
            }
            pos += __popc(mask);
        }
    }
}

// ---------------- kernel 2: tensor-core 3xTF32 GEMM -------------------------
// C[M,128] = H[M,K] @ W[K,128]; LAYER0: H = [ztab[z]|x] (K=256)
// k8-sliced, double-buffered SMEM; A stride 12, B stride 136 (conflict-free).
#define AS 12
#define BS 136
#define A_BUF (128 * AS)   // 1536 floats
#define B_BUF (8 * BS)     // 1088 floats
#define GEMM_SMEM ((2 * 2 * A_BUF + 2 * 2 * B_BUF) * 4)  // 41984 B

template <int LAYER0, int K>
__global__ void __launch_bounds__(256, 2) gemm_tc(
    const float* __restrict__ A_in, const int* __restrict__ z,
    const float* __restrict__ ztab, const float* __restrict__ xin,
    const float* __restrict__ W,    float* __restrict__ C, int M)
{
    extern __shared__ float sm[];
    // layout: Ah[2][A_BUF], Al[2][A_BUF], Bh[2][B_BUF], Bl[2][B_BUF]
    float* AH = sm;
    float* AL = AH + 2 * A_BUF;
    float* BH = AL + 2 * A_BUF;
    float* BL = BH + 2 * B_BUF;

    const int tid = threadIdx.x;
    const int lane = tid & 31, wid = tid >> 5;
    const int wm = wid & 1, wn = wid >> 1;      // 2 x 4 warp grid
    const int l4 = lane >> 2, lm = lane & 3;
    const int row0 = blockIdx.x * 128;

    // --- staging thread geometry ---
    const int st_row = tid >> 1;                 // A: 0..127
    const int st_c0  = (tid & 1) * 4;
    const int st_bk  = tid >> 5;                 // B: k row 0..7
    const int st_bn  = (tid & 31) * 4;

    const int gr  = row0 + st_row;
    const int grc = gr < M ? gr : (M - 1);
    const float* pz = nullptr;
    const float* px = nullptr;
    const float* pa = nullptr;
    if (LAYER0) {
        pz = ztab + (size_t)z[grc] * HID;
        px = xin + (size_t)grc * HID;
    } else {
        pa = A_in + (size_t)grc * K;
    }

    const int S = K / 8;

    auto stage = [&](int s, int p) {
        // A slice [128 x 8]
        int kk = s * 8 + st_c0;
        float4 v;
        if (LAYER0)
            v = (kk < 128) ? *(const float4*)(pz + kk)
                           : *(const float4*)(px + kk - 128);
        else
            v = *(const float4*)(pa + kk);
        float4 h, l;
        h.x = f2tf32f(v.x); l.x = v.x - h.x;
        h.y = f2tf32f(v.y); l.y = v.y - h.y;
        h.z = f2tf32f(v.z); l.z = v.z - h.z;
        h.w = f2tf32f(v.w); l.w = v.w - h.w;
        *(float4*)&AH[p * A_BUF + st_row * AS + st_c0] = h;
        *(float4*)&AL[p * A_BUF + st_row * AS + st_c0] = l;
        // B slice [8 x 128]
        float4 w4 = *(const float4*)(W + (size_t)(s * 8 + st_bk) * HID + st_bn);
        float4 wh, wl;
        wh.x = f2tf32f(w4.x); wl.x = w4.x - wh.x;
        wh.y = f2tf32f(w4.y); wl.y = w4.y - wh.y;
        wh.z = f2tf32f(w4.z); wl.z = w4.z - wh.z;
        wh.w = f2tf32f(w4.w); wl.w = w4.w - wh.w;
        *(float4*)&BH[p * B_BUF + st_bk * BS + st_bn] = wh;
        *(float4*)&BL[p * B_BUF + st_bk * BS + st_bn] = wl;
    };

    float acc[4][4][4];
#pragma unroll
    for (int mi = 0; mi < 4; mi++)
#pragma unroll
        for (int nj = 0; nj < 4; nj++)
#pragma unroll
            for (int q = 0; q < 4; q++) acc[mi][nj][q] = 0.f;

    stage(0, 0);

#pragma unroll 1
    for (int s = 0; s < S; s++) {
        __syncthreads();
        if (s + 1 < S) stage(s + 1, (s + 1) & 1);

        const int p = s & 1;
        const float* ah = AH + p * A_BUF;
        const float* al = AL + p * A_BUF;
        const float* bh = BH + p * B_BUF;
        const float* bl = BL + p * B_BUF;

        uint32_t a_h[4][4], a_l[4][4];
#pragma unroll
        for (int mi = 0; mi < 4; mi++) {
            int r = wm * 64 + mi * 16 + l4;
            a_h[mi][0] = __float_as_uint(ah[r * AS + lm]);
            a_h[mi][1] = __float_as_uint(ah[(r + 8) * AS + lm]);
            a_h[mi][2] = __float_as_uint(ah[r * AS + lm + 4]);
            a_h[mi][3] = __float_as_uint(ah[(r + 8) * AS + lm + 4]);
            a_l[mi][0] = __float_as_uint(al[r * AS + lm]);
            a_l[mi][1] = __float_as_uint(al[(r + 8) * AS + lm]);
            a_l[mi][2] = __float_as_uint(al[r * AS + lm + 4]);
            a_l[mi][3] = __float_as_uint(al[(r + 8) * AS + lm + 4]);
        }
#pragma unroll
        for (int nj = 0; nj < 4; nj++) {
            int n = wn * 32 + nj * 8 + l4;
            uint32_t bh0 = __float_as_uint(bh[lm * BS + n]);
            uint32_t bh1 = __float_as_uint(bh[(lm + 4) * BS + n]);
            uint32_t bl0 = __float_as_uint(bl[lm * BS + n]);
            uint32_t bl1 = __float_as_uint(bl[(lm + 4) * BS + n]);
#pragma unroll
            for (int mi = 0; mi < 4; mi++) {
                mma_tf32(acc[mi][nj], a_h[mi], bh0, bh1);
                mma_tf32(acc[mi][nj], a_h[mi], bl0, bl1);
                mma_tf32(acc[mi][nj], a_l[mi], bh0, bh1);
            }
        }
    }

    // ---- epilogue: direct stores -------------------------------------------
#pragma unroll
    for (int mi = 0; mi < 4; mi++) {
#pragma unroll
        for (int nj = 0; nj < 4; nj++) {
            int r = row0 + wm * 64 + mi * 16 + l4;
            int c = wn * 32 + nj * 8 + 2 * lm;
            if (r < M)
                *(float2*)(C + (size_t)r * HID + c) =
                    make_float2(acc[mi][nj][0], acc[mi][nj][1]);
            if (r + 8 < M)
                *(float2*)(C + (size_t)(r + 8) * HID + c) =
                    make_float2(acc[mi][nj][2], acc[mi][nj][3]);
        }
    }
}

// ---------------- kernel 3: X = tanh(A_norm @ T + b) per graph --------------
__global__ void __launch_bounds__(256) agg_tanh(
    const float* __restrict__ T, const float* __restrict__ bias,
    float* __restrict__ Xout)
{
    extern __shared__ float Ts[]; // [100][128]
    const int g = blockIdx.x, tid = threadIdx.x;
    const float* Tg = T + (size_t)g * NODES * HID;

    for (int t = tid; t < NODES * HID / 4; t += 256)
        ((float4*)Ts)[t] = ((const float4*)Tg)[t];
    __syncthreads();

    const int lane = tid & 31, warp = tid >> 5;
    const float4 bv = *(const float4*)(bias + lane * 4);
    const int2* ep  = g_edge + (size_t)g * EDGES;
    const int*  offp = g_off + g * 101;

    for (int d = warp; d < NODES; d += 8) {
        int e0 = offp[d], e1 = offp[d + 1];
        float4 a4 = make_float4(0.f, 0.f, 0.f, 0.f);
        for (int e = e0; e < e1; e++) {
            int2 pe = ep[e];
            float w = __int_as_float(pe.y);
            float4 tv = *(const float4*)&Ts[pe.x * HID + lane * 4];
            a4.x += w * tv.x; a4.y += w * tv.y;
            a4.z += w * tv.z; a4.w += w * tv.w;
        }
        float4 o;
        o.x = acc_tanh(a4.x + bv.x);
        o.y = acc_tanh(a4.y + bv.y);
        o.z = acc_tanh(a4.z + bv.z);
        o.w = acc_tanh(a4.w + bv.w);
        *(float4*)(Xout + ((size_t)g * NODES + d) * HID + lane * 4) = o;
    }
}

// ---------------- final: layer3 + sort-pool + conv + MLP --------------------
#define FINAL_SMEM_FLOATS 39028
__global__ void __launch_bounds__(256) final_k(
    const float* __restrict__ W3,  const float* __restrict__ b3,
    const float* __restrict__ cw1, const float* __restrict__ cb1,
    const float* __restrict__ cw2, const float* __restrict__ cb2,
    const float* __restrict__ mW1, const float* __restrict__ mb1,
    const float* __restrict__ mW2, const float* __restrict__ mb2,
    float* __restrict__ out)
{
    extern __shared__ float sm[];
    float* X2s  = sm;                  // 100*129
    float* cw1s = X2s + 100 * 129;     // 16*388 = 6208
    float* feat = cw1s + 6208;         // 40*388 = 15520
    float* cw2s = feat + 15520;        // 2560
    float* t3   = cw2s + 2560;         // 100
    float* x3   = t3 + 100;            // 100
    float* y1   = x3 + 100;            // 640
    float* mmp  = y1 + 640;            // 320
    float* flat = mmp + 320;           // 512
    float* rr   = flat + 512;          // 128
    int*   topi = (int*)(rr + 128);    // 40

    const int g = blockIdx.x, tid = threadIdx.x;
    const float* X2g = g_X2 + (size_t)g * NODES * HID;

    for (int t = tid; t < NODES * HID; t += 256) {
        int i = t >> 7, d = t & 127;
        X2s[i * 129 + d] = X2g[t];
    }
    for (int t = tid; t < 16 * 385; t += 256) {
        int c = t / 385, d = t - c * 385;
        cw1s[c * 388 + d] = cw1[t];
    }
    if (tid < 16) {
        cw1s[tid * 388 + 385] = 0.f;
        cw1s[tid * 388 + 386] = 0.f;
        cw1s[tid * 388 + 387] = 0.f;
    }
    for (int t = tid; t < 2560; t += 256) cw2s[t] = cw2[t];
    __syncthreads();

    if (tid < NODES) {
        float a = 0.f;
#pragma unroll 8
        for (int k = 0; k < HID; k++) a += X2s[tid * 129 + k] * W3[k];
        t3[tid] = a;
    }
    __syncthreads();

    if (tid < NODES) {
        const int*  offp = g_off + g * 101;
        const int2* ep   = g_edge + (size_t)g * EDGES;
        float a = 0.f;
        int e1 = offp[tid + 1];
        for (int e = offp[tid]; e < e1; e++) {
            int2 pe = ep[e];
            a += __int_as_float(pe.y) * t3[pe.x];
        }
        x3[tid] = acc_tanh(a + b3[0]);
    }
    __syncthreads();

    if (tid < NODES) {
        float v = x3[tid];
        int r = 0;
        for (int j = 0; j < NODES; j++) {
            float u = x3[j];
            r += (u > v) || (u == v && j < tid);
        }
        if (r < KTOP) topi[r] = tid;
    }
    __syncthreads();

    for (int t = tid; t < KTOP * HID; t += 256) {
        int k = t >> 7, d = t & 127;
        int node = topi[k];
        size_t gbase = ((size_t)g * NODES + node) * HID;
        feat[k * 388 + d]       = g_X0[gbase + d];
        feat[k * 388 + 128 + d] = g_X1[gbase + d];
        feat[k * 388 + 256 + d] = X2s[node * 129 + d];
    }
    if (tid < KTOP) {
        feat[tid * 388 + 384] = x3[topi[tid]];
        feat[tid * 388 + 385] = 0.f;
        feat[tid * 388 + 386] = 0.f;
        feat[tid * 388 + 387] = 0.f;
    }
    __syncthreads();

    for (int o = tid; o < 640; o += 256) {
        int c = o & 15, kp = o >> 4;
        float a = cb1[c];
        const float4* wr = (const float4*)(cw1s + c * 388);
        const float4* fr = (const float4*)(feat + kp * 388);
#pragma unroll 4
        for (int d = 0; d < 97; d++) {
            float4 w4 = wr[d], f4 = fr[d];
            a += w4.x * f4.x + w4.y * f4.y + w4.z * f4.z + w4.w * f4.w;
        }
        y1[c * 40 + kp] = fmaxf(a, 0.f);
    }
    __syncthreads();

    for (int t = tid; t < 320; t += 256) {
        int c = t / 20, p = t % 20;
        mmp[t] = fmaxf(y1[c * 40 + 2 * p], y1[c * 40 + 2 * p + 1]);
    }
    __syncthreads();

    for (int t = tid; t < 512; t += 256) {
        int o2 = t >> 4, p = t & 15;
        float a = cb2[o2];
#pragma unroll
        for (int c = 0; c < 16; c++)
#pragma unroll
            for (int u = 0; u < 5; u++)
                a += cw2s[(o2 * 16 + c) * 5 + u] * mmp[c * 20 + p + u];
        flat[t] = fmaxf(a, 0.f);
    }
    __syncthreads();

    {
        int col = tid & 127, half = tid >> 7;
        float a = 0.f;
        const float* fp = flat + half * 256;
        const float* wp = mW1 + (size_t)(half * 256) * 128 + col;
#pragma unroll 8
        for (int i = 0; i < 256; i++) a += fp[i] * wp[(size_t)i * 128];
        y1[tid] = a;
    }
    __syncthreads();
    if (tid < 128) rr[tid] = fmaxf(y1[tid] + y1[tid + 128] + mb1[tid], 0.f);
    __syncthreads();

    if (tid < 32) {
        float s = 0.f;
#pragma unroll
        for (int q = 0; q < 4; q++) s += rr[tid + 32 * q] * mW2[tid + 32 * q];
        for (int off2 = 16; off2 > 0; off2 >>= 1)
            s += __shfl_down_sync(0xffffffffu, s, off2);
        if (tid == 0) out[g] = s + mb2[0];
    }
}

// ---------------- host ------------------------------------------------------
extern "C" void kernel_launch(void* const* d_in, const int* in_sizes, int n_in,
                              void* d_out, int out_size)
{
    const float* x    = (const float*)d_in[0];
    const int*   z    = (const int*)  d_in[1];
    const int*   ei   = (const int*)  d_in[2];
    const float* ztab = (const float*)d_in[4];
    const float* W0   = (const float*)d_in[5];
    const float* b0   = (const float*)d_in[6];
    const float* W1   = (const float*)d_in[7];
    const float* b1   = (const float*)d_in[8];
    const float* W2   = (const float*)d_in[9];
    const float* b2   = (const float*)d_in[10];
    const float* W3   = (const float*)d_in[11];
    const float* b3   = (const float*)d_in[12];
    const float* cw1  = (const float*)d_in[13];
    const float* cb1  = (const float*)d_in[14];
    const float* cw2  = (const float*)d_in[15];
    const float* cb2  = (const float*)d_in[16];
    const float* mW1  = (const float*)d_in[17];
    const float* mb1  = (const float*)d_in[18];
    const float* mW2  = (const float*)d_in[19];
    const float* mb2  = (const float*)d_in[20];
    float* out = (float*)d_out;

    float *T, *X0, *X1, *X2;
    cudaGetSymbolAddress((void**)&T,  g_T);
    cudaGetSymbolAddress((void**)&X0, g_X0);
    cudaGetSymbolAddress((void**)&X1, g_X1);
    cudaGetSymbolAddress((void**)&X2, g_X2);

    cudaFuncSetAttribute(agg_tanh, cudaFuncAttributeMaxDynamicSharedMemorySize, 64 * 1024);
    cudaFuncSetAttribute(final_k,  cudaFuncAttributeMaxDynamicSharedMemorySize, 160 * 1024);

    const int GEMM_GRID = (NTOT + 127) / 128;
    const int AGG_SMEM  = NODES * HID * (int)sizeof(float); // 51200

    build_csr<<<NG, 256>>>(ei);

    gemm_tc<1, 256><<<GEMM_GRID, 256, GEMM_SMEM>>>(nullptr, z, ztab, x, W0, T, NTOT);
    agg_tanh<<<NG, 256, AGG_SMEM>>>(T, b0, X0);

    gemm_tc<0, 128><<<GEMM_GRID, 256, GEMM_SMEM>>>(X0, nullptr, nullptr, nullptr, W1, T, NTOT);
    agg_tanh<<<NG, 256, AGG_SMEM>>>(T, b1, X1);

    gemm_tc<0, 128><<<GEMM_GRID, 256, GEMM_SMEM>>>(X1, nullptr, nullptr, nullptr, W2, T, NTOT);
    agg_tanh<<<NG, 256, AGG_SMEM>>>(T, b2, X2);

    final_k<<<NG, 256, FINAL_SMEM_FLOATS * 4>>>(W3, b3, cw1, cb1, cw2, cb2,
                                                mW1, mb1, mW2, mb2, out);
}